// round 3
// baseline (speedup 1.0000x reference)
#include <cuda_runtime.h>
#include <math.h>

#define BB 1024
#define SS 64
#define EE 100
#define HH 512
#define H3 1536

// Scratch (static device arrays — no allocations allowed)
__device__ float g_gi[(size_t)3 * BB * SS * H3];   // [e][b*S+s][3H]  ~1.2 GB
__device__ float g_h[2][3 * BB * HH];              // double-buffered hidden
__device__ float g_eqc[BB * HH];

struct Enc {
    const int*   tok;
    const float* emb;
    const float* wih;
    const float* whh;
    const float* bih;
    const float* bhh;
};
struct EncPack { Enc e[3]; };

__device__ __forceinline__ float sigmoidf_(float x) {
    return 1.0f / (1.0f + __expf(-x));
}

// ---------------------------------------------------------------------------
// Zero initial hidden state
// ---------------------------------------------------------------------------
__global__ void zero_h_kernel() {
    size_t i = (size_t)blockIdx.x * blockDim.x + threadIdx.x;
    if (i < (size_t)3 * BB * HH) g_h[0][i] = 0.0f;
}

// ---------------------------------------------------------------------------
// GI kernel: gi[e, r, :] = emb[tok[r], :] @ wih^T + bih,  r in [0, B*S)
// Tile 64x64, K=100 (Kt=20), block 128 threads, micro-tile 8x4.
// grid: (H3/64=24, B*S/64=1024, 3)
// ---------------------------------------------------------------------------
__global__ __launch_bounds__(128) void gi_kernel(EncPack P) {
    const int e  = blockIdx.z;
    const Enc ep = P.e[e];
    const int n0 = blockIdx.x * 64;
    const int r0 = blockIdx.y * 64;

    __shared__ float As[20][65];
    __shared__ float Bs[20][65];
    __shared__ int   stok[64];

    const int tid = threadIdx.x;
    const int tx = tid & 15;      // 16 col-groups of 4
    const int ty = tid >> 4;      // 8 row-groups of 8

    if (tid < 64) stok[tid] = ep.tok[r0 + tid];
    __syncthreads();

    float acc[8][4];
#pragma unroll
    for (int i = 0; i < 8; i++)
#pragma unroll
        for (int j = 0; j < 4; j++) acc[i][j] = 0.0f;

    for (int k0 = 0; k0 < EE; k0 += 20) {
        for (int idx = tid; idx < 64 * 20; idx += 128) {
            int k = idx % 20, i = idx / 20;
            As[k][i] = ep.emb[(size_t)stok[i] * EE + (k0 + k)];
            Bs[k][i] = ep.wih[(size_t)(n0 + i) * EE + (k0 + k)];
        }
        __syncthreads();
#pragma unroll
        for (int k = 0; k < 20; k++) {
            float a[8], b[4];
#pragma unroll
            for (int i = 0; i < 8; i++) a[i] = As[k][ty * 8 + i];
#pragma unroll
            for (int j = 0; j < 4; j++) b[j] = Bs[k][tx * 4 + j];
#pragma unroll
            for (int i = 0; i < 8; i++)
#pragma unroll
                for (int j = 0; j < 4; j++) acc[i][j] += a[i] * b[j];
        }
        __syncthreads();
    }

    float bi[4];
#pragma unroll
    for (int j = 0; j < 4; j++) bi[j] = ep.bih[n0 + tx * 4 + j];

#pragma unroll
    for (int i = 0; i < 8; i++) {
        size_t base = ((size_t)e * (BB * SS) + (size_t)(r0 + ty * 8 + i)) * H3 + n0 + tx * 4;
#pragma unroll
        for (int j = 0; j < 4; j++) g_gi[base + j] = acc[i][j] + bi[j];
    }
}

// ---------------------------------------------------------------------------
// Step kernel (fused): gh = h @ whh^T ; gates ; h_new.
// Each thread's register tile covers the SAME j columns in all 3 gates,
// so the full GRU cell runs in registers (no gh scratch).
// Tile: 64 rows x 32 j-cols (x3 gates -> 96 GEMM cols), K=512 (Kt=16).
// Block 128 threads: ty in [0,8) -> 8 rows each; tx in [0,16) -> 2 j each.
// grid: (H/32=16, B/64=16, 3)
// ---------------------------------------------------------------------------
__global__ __launch_bounds__(128) void step_kernel(EncPack P, int t, int p) {
    const int e  = blockIdx.z;
    const Enc ep = P.e[e];
    const int j0 = blockIdx.x * 32;
    const int b0 = blockIdx.y * 64;

    const float* __restrict__ hin  = g_h[p]     + (size_t)e * (BB * HH);
    float*       __restrict__ hout = g_h[p ^ 1] + (size_t)e * (BB * HH);

    __shared__ float As[16][65];   // [k][row]
    __shared__ float Bs[16][97];   // [k][gate*32 + jj]

    const int tid = threadIdx.x;
    const int tx = tid & 15;
    const int ty = tid >> 4;

    float acc[8][6];   // [row][gate*2 + jj]
#pragma unroll
    for (int i = 0; i < 8; i++)
#pragma unroll
        for (int c = 0; c < 6; c++) acc[i][c] = 0.0f;

    for (int k0 = 0; k0 < HH; k0 += 16) {
#pragma unroll
        for (int l = 0; l < 8; l++) {       // 64x16 = 1024 elems
            int idx = tid + l * 128;
            int k = idx & 15, i = idx >> 4;
            As[k][i] = hin[(size_t)(b0 + i) * HH + (k0 + k)];
        }
#pragma unroll
        for (int l = 0; l < 12; l++) {      // 96x16 = 1536 elems
            int idx = tid + l * 128;
            int k = idx & 15, c = idx >> 4;     // c in [0,96)
            int g = c >> 5, jj = c & 31;
            Bs[k][c] = ep.whh[(size_t)(g * HH + j0 + jj) * HH + (k0 + k)];
        }
        __syncthreads();
#pragma unroll
        for (int k = 0; k < 16; k++) {
            float a[8], b[6];
#pragma unroll
            for (int i = 0; i < 8; i++) a[i] = As[k][ty * 8 + i];
#pragma unroll
            for (int g = 0; g < 3; g++) {
                b[g * 2 + 0] = Bs[k][g * 32 + tx * 2 + 0];
                b[g * 2 + 1] = Bs[k][g * 32 + tx * 2 + 1];
            }
#pragma unroll
            for (int i = 0; i < 8; i++)
#pragma unroll
                for (int c = 0; c < 6; c++) acc[i][c] += a[i] * b[c];
        }
        __syncthreads();
    }

    // Gate math, fully in registers
    const int jc = j0 + tx * 2;
    float bh[6];
#pragma unroll
    for (int g = 0; g < 3; g++) {
        bh[g * 2 + 0] = ep.bhh[g * HH + jc + 0];
        bh[g * 2 + 1] = ep.bhh[g * HH + jc + 1];
    }

#pragma unroll
    for (int i = 0; i < 8; i++) {
        int row = b0 + ty * 8 + i;
        size_t gbase = ((size_t)e * (BB * SS) + (size_t)row * SS + t) * H3;
#pragma unroll
        for (int jj = 0; jj < 2; jj++) {
            int col = jc + jj;
            float gir = g_gi[gbase + col];
            float giz = g_gi[gbase + HH + col];
            float gin = g_gi[gbase + 2 * HH + col];
            float rr = sigmoidf_(gir + acc[i][0 + jj] + bh[0 + jj]);
            float zz = sigmoidf_(giz + acc[i][2 + jj] + bh[2 + jj]);
            float nn = tanhf(gin + rr * (acc[i][4 + jj] + bh[4 + jj]));
            float hold = hin[(size_t)row * HH + col];
            hout[(size_t)row * HH + col] = (1.0f - zz) * nn + zz * hold;
        }
    }
}

// ---------------------------------------------------------------------------
// eqc = ((eq + ec) * 0.5) @ lin_w^T + lin_b    [1024,512]x[512,512]
// grid: (512/64=8, 1024/64=16), block 128, micro 8x4
// ---------------------------------------------------------------------------
__global__ __launch_bounds__(128) void eqc_kernel(const float* __restrict__ lin_w,
                                                  const float* __restrict__ lin_b,
                                                  int p) {
    const float* __restrict__ hq = g_h[p];
    const float* __restrict__ hc = g_h[p] + (size_t)BB * HH;
    const int n0 = blockIdx.x * 64;
    const int b0 = blockIdx.y * 64;

    __shared__ float As[16][65];
    __shared__ float Bs[16][65];

    const int tid = threadIdx.x;
    const int tx = tid & 15, ty = tid >> 4;

    float acc[8][4];
#pragma unroll
    for (int i = 0; i < 8; i++)
#pragma unroll
        for (int j = 0; j < 4; j++) acc[i][j] = 0.0f;

    for (int k0 = 0; k0 < HH; k0 += 16) {
#pragma unroll
        for (int l = 0; l < 8; l++) {
            int idx = tid + l * 128;
            int k = idx & 15, i = idx >> 4;
            size_t ga = (size_t)(b0 + i) * HH + (k0 + k);
            As[k][i] = 0.5f * (hq[ga] + hc[ga]);
            Bs[k][i] = lin_w[(size_t)(n0 + i) * HH + (k0 + k)];
        }
        __syncthreads();
#pragma unroll
        for (int k = 0; k < 16; k++) {
            float a[8], b[4];
#pragma unroll
            for (int i = 0; i < 8; i++) a[i] = As[k][ty * 8 + i];
#pragma unroll
            for (int j = 0; j < 4; j++) b[j] = Bs[k][tx * 4 + j];
#pragma unroll
            for (int i = 0; i < 8; i++)
#pragma unroll
                for (int j = 0; j < 4; j++) acc[i][j] += a[i] * b[j];
        }
        __syncthreads();
    }

    float bi[4];
#pragma unroll
    for (int j = 0; j < 4; j++) bi[j] = lin_b[n0 + tx * 4 + j];
#pragma unroll
    for (int i = 0; i < 8; i++) {
        size_t base = (size_t)(b0 + ty * 8 + i) * HH + n0 + tx * 4;
#pragma unroll
        for (int j = 0; j < 4; j++) g_eqc[base + j] = acc[i][j] + bi[j];
    }
}

// ---------------------------------------------------------------------------
// logits[m] = X_m @ er^T   (X in {eq, ec, eqc}), [1024,512]x[512,1024]
// grid: (1024/64=16, 1024/64=16, 3), block 128, micro 8x4. Writes d_out.
// ---------------------------------------------------------------------------
__global__ __launch_bounds__(128) void logits_kernel(float* __restrict__ out, int p) {
    const int m = blockIdx.z;
    const float* __restrict__ X  = (m == 0) ? g_h[p]
                                 : (m == 1) ? g_h[p] + (size_t)BB * HH
                                            : g_eqc;
    const float* __restrict__ er = g_h[p] + (size_t)2 * BB * HH;
    const int n0 = blockIdx.x * 64;
    const int b0 = blockIdx.y * 64;

    __shared__ float As[16][65];
    __shared__ float Bs[16][65];

    const int tid = threadIdx.x;
    const int tx = tid & 15, ty = tid >> 4;

    float acc[8][4];
#pragma unroll
    for (int i = 0; i < 8; i++)
#pragma unroll
        for (int j = 0; j < 4; j++) acc[i][j] = 0.0f;

    for (int k0 = 0; k0 < HH; k0 += 16) {
#pragma unroll
        for (int l = 0; l < 8; l++) {
            int idx = tid + l * 128;
            int k = idx & 15, i = idx >> 4;
            As[k][i] = X[(size_t)(b0 + i) * HH + (k0 + k)];
            Bs[k][i] = er[(size_t)(n0 + i) * HH + (k0 + k)];
        }
        __syncthreads();
#pragma unroll
        for (int k = 0; k < 16; k++) {
            float a[8], b[4];
#pragma unroll
            for (int i = 0; i < 8; i++) a[i] = As[k][ty * 8 + i];
#pragma unroll
            for (int j = 0; j < 4; j++) b[j] = Bs[k][tx * 4 + j];
#pragma unroll
            for (int i = 0; i < 8; i++)
#pragma unroll
                for (int j = 0; j < 4; j++) acc[i][j] += a[i] * b[j];
        }
        __syncthreads();
    }

#pragma unroll
    for (int i = 0; i < 8; i++) {
        size_t base = (size_t)m * BB * BB + (size_t)(b0 + ty * 8 + i) * BB + n0 + tx * 4;
#pragma unroll
        for (int j = 0; j < 4; j++) out[base + j] = acc[i][j];
    }
}

// ---------------------------------------------------------------------------
// Row softmax over 3*B rows of length B, in-place on d_out.
// ---------------------------------------------------------------------------
__global__ __launch_bounds__(256) void softmax_kernel(float* __restrict__ out) {
    float* prow = out + (size_t)blockIdx.x * BB;
    __shared__ float red[256];
    const int tid = threadIdx.x;

    float v[4];
    float mx = -1e30f;
#pragma unroll
    for (int l = 0; l < 4; l++) {
        v[l] = prow[tid + l * 256];
        mx = fmaxf(mx, v[l]);
    }
    red[tid] = mx;
    __syncthreads();
    for (int s = 128; s > 0; s >>= 1) {
        if (tid < s) red[tid] = fmaxf(red[tid], red[tid + s]);
        __syncthreads();
    }
    mx = red[0];
    __syncthreads();

    float sum = 0.0f;
#pragma unroll
    for (int l = 0; l < 4; l++) {
        v[l] = __expf(v[l] - mx);
        sum += v[l];
    }
    red[tid] = sum;
    __syncthreads();
    for (int s = 128; s > 0; s >>= 1) {
        if (tid < s) red[tid] += red[tid + s];
        __syncthreads();
    }
    float inv = 1.0f / red[0];
#pragma unroll
    for (int l = 0; l < 4; l++) prow[tid + l * 256] = v[l] * inv;
}

// ---------------------------------------------------------------------------
// Launch
// ---------------------------------------------------------------------------
extern "C" void kernel_launch(void* const* d_in, const int* in_sizes, int n_in,
                              void* d_out, int out_size) {
    (void)in_sizes; (void)n_in; (void)out_size;

    EncPack P;
    const int* toks[3] = { (const int*)d_in[0], (const int*)d_in[1], (const int*)d_in[2] };
    for (int e = 0; e < 3; e++) {
        int b = 3 + e * 5;
        P.e[e].tok = toks[e];
        P.e[e].emb = (const float*)d_in[b + 0];
        P.e[e].wih = (const float*)d_in[b + 1];
        P.e[e].whh = (const float*)d_in[b + 2];
        P.e[e].bih = (const float*)d_in[b + 3];
        P.e[e].bhh = (const float*)d_in[b + 4];
    }
    const float* lin_w = (const float*)d_in[18];
    const float* lin_b = (const float*)d_in[19];
    float* out = (float*)d_out;

    zero_h_kernel<<<(3 * BB * HH + 255) / 256, 256>>>();

    gi_kernel<<<dim3(H3 / 64, (BB * SS) / 64, 3), 128>>>(P);

    int p = 0;
    for (int t = SS - 1; t >= 0; --t) {
        step_kernel<<<dim3(HH / 32, BB / 64, 3), 128>>>(P, t, p);
        p ^= 1;
    }

    eqc_kernel<<<dim3(HH / 64, BB / 64), 128>>>(lin_w, lin_b, p);
    logits_kernel<<<dim3(BB / 64, BB / 64, 3), 128>>>(out, p);
    softmax_kernel<<<3 * BB, 256>>>(out);
}

// round 5
// speedup vs baseline: 2.6147x; 2.6147x over previous
#include <cuda_runtime.h>
#include <cstdint>
#include <math.h>

#define BB 1024
#define SS 64
#define EE 100
#define HH 512

// Scratch (static device arrays — no allocations allowed)
__device__ float g_h[2][3 * BB * HH];              // double-buffered hidden
__device__ float g_eqc[BB * HH];

struct Enc {
    const int*   tok;
    const float* emb;
    const float* wih;
    const float* whh;
    const float* bih;
    const float* bhh;
};
struct EncPack { Enc e[3]; };

__device__ __forceinline__ float sigmoidf_(float x) {
    return 1.0f / (1.0f + __expf(-x));
}

// ===========================================================================
// PTX helpers (sm_80-compatible only: cp.async + mma.sync tf32)
// ===========================================================================
__device__ __forceinline__ uint32_t smem_u32(const void* p) {
    uint32_t a;
    asm("{ .reg .u64 t; cvta.to.shared.u64 t, %1; cvt.u32.u64 %0, t; }" : "=r"(a) : "l"(p));
    return a;
}

__device__ __forceinline__ void cp16(uint32_t dst, const void* src, uint32_t sz) {
    asm volatile("cp.async.cg.shared.global [%0], [%1], 16, %2;"
                 :: "r"(dst), "l"(src), "r"(sz));
}
#define CP_COMMIT() asm volatile("cp.async.commit_group;" ::: "memory")
#define CP_WAIT1()  asm volatile("cp.async.wait_group 1;" ::: "memory")

__device__ __forceinline__ uint32_t f2tf(float x) {
    uint32_t r;
    asm("cvt.rna.tf32.f32 %0, %1;" : "=r"(r) : "f"(x));
    return r;
}

__device__ __forceinline__ void mma8(float* d, const uint32_t* a, uint32_t b0, uint32_t b1) {
    asm volatile("mma.sync.aligned.m16n8k8.row.col.f32.tf32.tf32.f32 "
                 "{%0,%1,%2,%3}, {%4,%5,%6,%7}, {%8,%9}, {%0,%1,%2,%3};"
                 : "+f"(d[0]), "+f"(d[1]), "+f"(d[2]), "+f"(d[3])
                 : "r"(a[0]), "r"(a[1]), "r"(a[2]), "r"(a[3]), "r"(b0), "r"(b1));
}

// ===========================================================================
// Zero initial hidden state
// ===========================================================================
__global__ void zero_h_kernel() {
    size_t i = (size_t)blockIdx.x * blockDim.x + threadIdx.x;
    if (i < (size_t)3 * BB * HH) g_h[0][i] = 0.0f;
}

// ===========================================================================
// Fused GRU step on tensor cores (mma.sync tf32).
//
// Per CTA: M=128 batch rows x N=128 GEMM cols, K=640 (512 h + 128 x-pad).
// N columns, section-interleaved per 8-j group:
//   n-tile nt (8 cols each): jg = nt>>2, sec = nt&3, j = j0 + jg*8 + (n&7)
//   sec 0: r gate   (h@whh_r + x@wih_r)
//   sec 1: z gate   (h@whh_z + x@wih_z)
//   sec 2: h_n      (h@whh_n)
//   sec 3: i_n      (x@wih_n)
// 8 warps: warp_m in [0,4) -> 32 rows; warp_n in [0,2) -> 64 cols
//   (= 2 j-groups with ALL four sections -> gate math fully in-register).
// grid: (HH/32=16, BB/128=8, 3), block 256.
// ===========================================================================
#define PADK 20                 // floats per smem row (80B, 16B-aligned, conflict-free)
#define KCH  16                 // K per chunk
#define NCHK 40                 // 32 h-chunks + 8 x-chunks

__global__ __launch_bounds__(256, 2) void step_tc_kernel(EncPack P, int t, int p) {
    __shared__ float As[2][128 * PADK];
    __shared__ float Bs[2][128 * PADK];
    __shared__ int   stok[128];

    const int e  = blockIdx.z;
    const Enc ep = P.e[e];
    const int j0 = blockIdx.x * 32;
    const int b0 = blockIdx.y * 128;

    const float* __restrict__ hin  = g_h[p]     + (size_t)e * (BB * HH);
    float*       __restrict__ hout = g_h[p ^ 1] + (size_t)e * (BB * HH);

    const int tid = threadIdx.x;
    const int wid = tid >> 5;
    const int lane = tid & 31;
    const int gr = lane >> 2;        // groupID
    const int tg = lane & 3;         // threadID_in_group
    const int warp_m = wid & 3;
    const int warp_n = wid >> 2;

    const uint32_t sA = smem_u32(As);
    const uint32_t sB = smem_u32(Bs);

    if (tid < 128) stok[tid] = ep.tok[(b0 + tid) * SS + t];
    __syncthreads();

    float acc[2][2][4][4];           // [mt][jg_l][sec][dreg]
#pragma unroll
    for (int a = 0; a < 2; a++)
#pragma unroll
        for (int b = 0; b < 2; b++)
#pragma unroll
            for (int s = 0; s < 4; s++)
#pragma unroll
                for (int k = 0; k < 4; k++) acc[a][b][s][k] = 0.0f;

    // ---- async loader for chunk c into stage st ----
    auto load_chunk = [&](int c, int st) {
        const uint32_t aBase = sA + (uint32_t)st * 128 * PADK * 4;
        const uint32_t bBase = sB + (uint32_t)st * 128 * PADK * 4;
#pragma unroll
        for (int it = 0; it < 2; it++) {
            int idx = tid + it * 256;            // [0,512)
            int row = idx >> 2, kq = idx & 3;    // kq: float4 index within 16
            uint32_t dstA = aBase + (uint32_t)(row * PADK + kq * 4) * 4;
            uint32_t dstB = bBase + (uint32_t)(row * PADK + kq * 4) * 4;
            if (c < 32) {
                int k0 = c * KCH + kq * 4;
                cp16(dstA, hin + (size_t)(b0 + row) * HH + k0, 16);
                // B: row = n-col; sections
                int n = row;
                int sec = (n >> 3) & 3, jg = n >> 5, j = j0 + jg * 8 + (n & 7);
                if (sec < 3)
                    cp16(dstB, ep.whh + (size_t)(sec * HH + j) * HH + k0, 16);
                else
                    cp16(dstB, ep.whh, 0);
            } else {
                int col = (c - 32) * KCH + kq * 4;     // [0,128) into E=100 padded
                uint32_t vs = (col <= 96) ? 16u : 0u;
                cp16(dstA, vs ? (ep.emb + (size_t)stok[row] * EE + col) : ep.emb, vs);
                int n = row;
                int sec = (n >> 3) & 3, jg = n >> 5, j = j0 + jg * 8 + (n & 7);
                int wrow = (sec == 0) ? j : (sec == 1) ? (HH + j)
                         : (sec == 3) ? (2 * HH + j) : -1;
                uint32_t vb = (wrow >= 0 && col <= 96) ? 16u : 0u;
                cp16(dstB, vb ? (ep.wih + (size_t)wrow * EE + col) : ep.wih, vb);
            }
        }
    };

    load_chunk(0, 0);
    CP_COMMIT();

    for (int c = 0; c < NCHK; c++) {
        if (c + 1 < NCHK) load_chunk(c + 1, (c + 1) & 1);
        CP_COMMIT();
        CP_WAIT1();
        __syncthreads();

        const float* Ast = As[c & 1];
        const float* Bst = Bs[c & 1];

#pragma unroll
        for (int k8 = 0; k8 < KCH; k8 += 8) {
            uint32_t afr[2][4];
#pragma unroll
            for (int mt = 0; mt < 2; mt++) {
                int rb = warp_m * 32 + mt * 16 + gr;
                afr[mt][0] = f2tf(Ast[(rb)     * PADK + k8 + tg]);
                afr[mt][1] = f2tf(Ast[(rb + 8) * PADK + k8 + tg]);
                afr[mt][2] = f2tf(Ast[(rb)     * PADK + k8 + tg + 4]);
                afr[mt][3] = f2tf(Ast[(rb + 8) * PADK + k8 + tg + 4]);
            }
#pragma unroll
            for (int ntl = 0; ntl < 8; ntl++) {
                int n = warp_n * 64 + ntl * 8 + gr;
                uint32_t b0r = f2tf(Bst[n * PADK + k8 + tg]);
                uint32_t b1r = f2tf(Bst[n * PADK + k8 + tg + 4]);
                int jg_l = ntl >> 2, sec = ntl & 3;
                mma8(acc[0][jg_l][sec], afr[0], b0r, b1r);
                mma8(acc[1][jg_l][sec], afr[1], b0r, b1r);
            }
        }
        __syncthreads();
    }

    // ---- GRU epilogue, fully in-register per thread ----
#pragma unroll
    for (int jg_l = 0; jg_l < 2; jg_l++) {
#pragma unroll
        for (int cc = 0; cc < 2; cc++) {
            const int j = j0 + (warp_n * 2 + jg_l) * 8 + tg * 2 + cc;
            const float br  = ep.bih[j]          + ep.bhh[j];
            const float bz  = ep.bih[HH + j]     + ep.bhh[HH + j];
            const float bhn = ep.bhh[2 * HH + j];
            const float bin = ep.bih[2 * HH + j];
#pragma unroll
            for (int mt = 0; mt < 2; mt++) {
#pragma unroll
                for (int rp = 0; rp < 2; rp++) {
                    const int row = b0 + warp_m * 32 + mt * 16 + gr + rp * 8;
                    const int k = rp * 2 + cc;
                    float r  = sigmoidf_(acc[mt][jg_l][0][k] + br);
                    float z  = sigmoidf_(acc[mt][jg_l][1][k] + bz);
                    float n  = tanhf(acc[mt][jg_l][3][k] + bin + r * (acc[mt][jg_l][2][k] + bhn));
                    float ho = hin[(size_t)row * HH + j];
                    hout[(size_t)row * HH + j] = (1.0f - z) * n + z * ho;
                }
            }
        }
    }
}

// ===========================================================================
// eqc = ((eq + ec) * 0.5) @ lin_w^T + lin_b    [1024,512]x[512,512]
// ===========================================================================
__global__ __launch_bounds__(128) void eqc_kernel(const float* __restrict__ lin_w,
                                                  const float* __restrict__ lin_b,
                                                  int p) {
    const float* __restrict__ hq = g_h[p];
    const float* __restrict__ hc = g_h[p] + (size_t)BB * HH;
    const int n0 = blockIdx.x * 64;
    const int b0 = blockIdx.y * 64;

    __shared__ float As[16][65];
    __shared__ float Bs[16][65];

    const int tid = threadIdx.x;
    const int tx = tid & 15, ty = tid >> 4;

    float acc[8][4];
#pragma unroll
    for (int i = 0; i < 8; i++)
#pragma unroll
        for (int j = 0; j < 4; j++) acc[i][j] = 0.0f;

    for (int k0 = 0; k0 < HH; k0 += 16) {
#pragma unroll
        for (int l = 0; l < 8; l++) {
            int idx = tid + l * 128;
            int k = idx & 15, i = idx >> 4;
            size_t ga = (size_t)(b0 + i) * HH + (k0 + k);
            As[k][i] = 0.5f * (hq[ga] + hc[ga]);
            Bs[k][i] = lin_w[(size_t)(n0 + i) * HH + (k0 + k)];
        }
        __syncthreads();
#pragma unroll
        for (int k = 0; k < 16; k++) {
            float a[8], b[4];
#pragma unroll
            for (int i = 0; i < 8; i++) a[i] = As[k][ty * 8 + i];
#pragma unroll
            for (int j = 0; j < 4; j++) b[j] = Bs[k][tx * 4 + j];
#pragma unroll
            for (int i = 0; i < 8; i++)
#pragma unroll
                for (int j = 0; j < 4; j++) acc[i][j] += a[i] * b[j];
        }
        __syncthreads();
    }

    float bi[4];
#pragma unroll
    for (int j = 0; j < 4; j++) bi[j] = lin_b[n0 + tx * 4 + j];
#pragma unroll
    for (int i = 0; i < 8; i++) {
        size_t base = (size_t)(b0 + ty * 8 + i) * HH + n0 + tx * 4;
#pragma unroll
        for (int j = 0; j < 4; j++) g_eqc[base + j] = acc[i][j] + bi[j];
    }
}

// ===========================================================================
// logits[m] = X_m @ er^T   (X in {eq, ec, eqc}), writes d_out
// ===========================================================================
__global__ __launch_bounds__(128) void logits_kernel(float* __restrict__ out, int p) {
    const int m = blockIdx.z;
    const float* __restrict__ X  = (m == 0) ? g_h[p]
                                 : (m == 1) ? g_h[p] + (size_t)BB * HH
                                            : g_eqc;
    const float* __restrict__ er = g_h[p] + (size_t)2 * BB * HH;
    const int n0 = blockIdx.x * 64;
    const int b0 = blockIdx.y * 64;

    __shared__ float As[16][65];
    __shared__ float Bs[16][65];

    const int tid = threadIdx.x;
    const int tx = tid & 15, ty = tid >> 4;

    float acc[8][4];
#pragma unroll
    for (int i = 0; i < 8; i++)
#pragma unroll
        for (int j = 0; j < 4; j++) acc[i][j] = 0.0f;

    for (int k0 = 0; k0 < HH; k0 += 16) {
#pragma unroll
        for (int l = 0; l < 8; l++) {
            int idx = tid + l * 128;
            int k = idx & 15, i = idx >> 4;
            As[k][i] = X[(size_t)(b0 + i) * HH + (k0 + k)];
            Bs[k][i] = er[(size_t)(n0 + i) * HH + (k0 + k)];
        }
        __syncthreads();
#pragma unroll
        for (int k = 0; k < 16; k++) {
            float a[8], b[4];
#pragma unroll
            for (int i = 0; i < 8; i++) a[i] = As[k][ty * 8 + i];
#pragma unroll
            for (int j = 0; j < 4; j++) b[j] = Bs[k][tx * 4 + j];
#pragma unroll
            for (int i = 0; i < 8; i++)
#pragma unroll
                for (int j = 0; j < 4; j++) acc[i][j] += a[i] * b[j];
        }
        __syncthreads();
    }

#pragma unroll
    for (int i = 0; i < 8; i++) {
        size_t base = (size_t)m * BB * BB + (size_t)(b0 + ty * 8 + i) * BB + n0 + tx * 4;
#pragma unroll
        for (int j = 0; j < 4; j++) out[base + j] = acc[i][j];
    }
}

// ===========================================================================
// Row softmax over 3*B rows of length B, in-place on d_out.
// ===========================================================================
__global__ __launch_bounds__(256) void softmax_kernel(float* __restrict__ out) {
    float* prow = out + (size_t)blockIdx.x * BB;
    __shared__ float red[256];
    const int tid = threadIdx.x;

    float v[4];
    float mx = -1e30f;
#pragma unroll
    for (int l = 0; l < 4; l++) {
        v[l] = prow[tid + l * 256];
        mx = fmaxf(mx, v[l]);
    }
    red[tid] = mx;
    __syncthreads();
    for (int s = 128; s > 0; s >>= 1) {
        if (tid < s) red[tid] = fmaxf(red[tid], red[tid + s]);
        __syncthreads();
    }
    mx = red[0];
    __syncthreads();

    float sum = 0.0f;
#pragma unroll
    for (int l = 0; l < 4; l++) {
        v[l] = __expf(v[l] - mx);
        sum += v[l];
    }
    red[tid] = sum;
    __syncthreads();
    for (int s = 128; s > 0; s >>= 1) {
        if (tid < s) red[tid] += red[tid + s];
        __syncthreads();
    }
    float inv = 1.0f / red[0];
#pragma unroll
    for (int l = 0; l < 4; l++) prow[tid + l * 256] = v[l] * inv;
}

// ===========================================================================
// Launch
// ===========================================================================
extern "C" void kernel_launch(void* const* d_in, const int* in_sizes, int n_in,
                              void* d_out, int out_size) {
    (void)in_sizes; (void)n_in; (void)out_size;

    EncPack P;
    const int* toks[3] = { (const int*)d_in[0], (const int*)d_in[1], (const int*)d_in[2] };
    for (int e = 0; e < 3; e++) {
        int b = 3 + e * 5;
        P.e[e].tok = toks[e];
        P.e[e].emb = (const float*)d_in[b + 0];
        P.e[e].wih = (const float*)d_in[b + 1];
        P.e[e].whh = (const float*)d_in[b + 2];
        P.e[e].bih = (const float*)d_in[b + 3];
        P.e[e].bhh = (const float*)d_in[b + 4];
    }
    const float* lin_w = (const float*)d_in[18];
    const float* lin_b = (const float*)d_in[19];
    float* out = (float*)d_out;

    zero_h_kernel<<<(3 * BB * HH + 255) / 256, 256>>>();

    int p = 0;
    for (int t = SS - 1; t >= 0; --t) {
        step_tc_kernel<<<dim3(HH / 32, BB / 128, 3), 256>>>(P, t, p);
        p ^= 1;
    }

    eqc_kernel<<<dim3(HH / 64, BB / 64), 128>>>(lin_w, lin_b, p);
    logits_kernel<<<dim3(BB / 64, BB / 64, 3), 128>>>(out, p);
    softmax_kernel<<<3 * BB, 256>>>(out);
}